// round 12
// baseline (speedup 1.0000x reference)
#include <cuda_runtime.h>

// LayerNorm backward fused: golden_x [B,S,H], golden_gamma [H], golden_beta [H]
// B=4, S=4096, H=2048, fp32. Output layout: [x | gamma | beta] concatenated.
// R11: R9 kernel (2 CTAs/SM x 256 thr, distance-2 register prefetch,
//      127 regs) + zero-register L2 software prefetch: dy/x1/x2 at
//      distance 4, dsum at distance 2. Memset node for param grads.

#define HF 2048
#define ROWS 16384           // B*S
#define THREADS 256
#define GRID 296             // 148 SMs * 2 CTAs/SM

__global__ __launch_bounds__(THREADS, 2) void ln_bwd_kernel(
    const float* __restrict__ dy,
    const float* __restrict__ x1,
    const float* __restrict__ x2,
    const float* __restrict__ rstd,
    const float* __restrict__ mean,
    const float* __restrict__ gamma,
    const float* __restrict__ dsum,
    float* __restrict__ out)
{
    __shared__ float red[2][3][8];

    const int tid  = threadIdx.x;
    const int lane = tid & 31;
    const int wid  = tid >> 5;
    const int bid  = blockIdx.x;

    const int c0 = 4 * tid;          // 0..1020
    const int c1 = c0 + HF / 2;      // 1024..2044

    const float4 g0 = *(const float4*)(gamma + c0);
    const float4 g1 = *(const float4*)(gamma + c1);
    float gv[8] = {g0.x, g0.y, g0.z, g0.w, g1.x, g1.y, g1.z, g1.w};

    float ag[8] = {0.f, 0.f, 0.f, 0.f, 0.f, 0.f, 0.f, 0.f};
    float ab[8] = {0.f, 0.f, 0.f, 0.f, 0.f, 0.f, 0.f, 0.f};

    const float inv_d = 1.0f / (float)HF;

    // ---- two register buffer sets: dy, x1, x2 (+ mean/rstd scalars) ----
    float4 Ady0, Ady1, Aa0, Aa1, Ab0, Ab1; float Amu = 0.f, Ars = 0.f;
    float4 Bdy0, Bdy1, Ba0, Ba1, Bb0, Bb1; float Bmu = 0.f, Brs = 0.f;

    #define PF_L2(p) asm volatile("prefetch.global.L2 [%0];" :: "l"(p))

    #define LOADBUF(P, row)                                                  \
        if ((row) < ROWS) {                                                  \
            const size_t _b = (size_t)(row) * HF;                            \
            P##dy0 = __ldcs((const float4*)(dy + _b + c0));                  \
            P##dy1 = __ldcs((const float4*)(dy + _b + c1));                  \
            P##a0  = __ldcs((const float4*)(x1 + _b + c0));                  \
            P##a1  = __ldcs((const float4*)(x1 + _b + c1));                  \
            P##b0  = __ldcs((const float4*)(x2 + _b + c0));                  \
            P##b1  = __ldcs((const float4*)(x2 + _b + c1));                  \
            P##mu  = __ldcs(mean + (row));                                   \
            P##rs  = __ldcs(rstd + (row));                                   \
        }

    // Consume buffer P (row `row`), refill P for row `nrow` (= row+2*GRID),
    // L2-prefetch row+4*GRID (dy/x1/x2) and row+2*GRID (dsum), do row work.
    #define STEP(P, row, nrow, PAR)                                          \
    {                                                                        \
        const size_t base = (size_t)(row) * HF;                              \
        /* consume buffer into locals (frees P for the refill below) */      \
        float dyv[8] = {P##dy0.x, P##dy0.y, P##dy0.z, P##dy0.w,              \
                        P##dy1.x, P##dy1.y, P##dy1.z, P##dy1.w};             \
        const float mu = P##mu;                                              \
        const float rs = P##rs;                                              \
        float xh[8]  = {P##a0.x + P##b0.x - mu, P##a0.y + P##b0.y - mu,      \
                        P##a0.z + P##b0.z - mu, P##a0.w + P##b0.w - mu,      \
                        P##a1.x + P##b1.x - mu, P##a1.y + P##b1.y - mu,      \
                        P##a1.z + P##b1.z - mu, P##a1.w + P##b1.w - mu};     \
        /* dsum for THIS row: issued now, consumed post-barrier */           \
        const float4 ds0 = __ldcs((const float4*)(dsum + base + c0));        \
        const float4 ds1 = __ldcs((const float4*)(dsum + base + c1));        \
        /* refill buffer: distance-2 register prefetch */                    \
        LOADBUF(P, nrow);                                                    \
        /* zero-register L2 prefetch: distance 4 (dy/x1/x2), 2 (dsum) */     \
        if ((row) + 4 * GRID < ROWS) {                                       \
            const size_t _b4 = (size_t)((row) + 4 * GRID) * HF;              \
            PF_L2(dy + _b4 + c0);  PF_L2(dy + _b4 + c1);                     \
            PF_L2(x1 + _b4 + c0);  PF_L2(x1 + _b4 + c1);                     \
            PF_L2(x2 + _b4 + c0);  PF_L2(x2 + _b4 + c1);                     \
        }                                                                    \
        if ((row) + 2 * GRID < ROWS) {                                       \
            const size_t _b2 = (size_t)((row) + 2 * GRID) * HF;              \
            PF_L2(dsum + _b2 + c0); PF_L2(dsum + _b2 + c1);                  \
        }                                                                    \
        /* local partial sums */                                             \
        float s1 = 0.f, s2 = 0.f, s3 = 0.f;                                  \
        _Pragma("unroll")                                                    \
        for (int k = 0; k < 8; k++) {                                        \
            const float pdxl = dyv[k] * gv[k];                               \
            s1 = fmaf(pdxl, xh[k], s1);                                      \
            s2 += pdxl;                                                      \
            s3 += xh[k];                                                     \
        }                                                                    \
        _Pragma("unroll")                                                    \
        for (int off = 16; off > 0; off >>= 1) {                             \
            s1 += __shfl_xor_sync(0xFFFFFFFFu, s1, off);                     \
            s2 += __shfl_xor_sync(0xFFFFFFFFu, s2, off);                     \
            s3 += __shfl_xor_sync(0xFFFFFFFFu, s3, off);                     \
        }                                                                    \
        if (lane == 0) {                                                     \
            red[PAR][0][wid] = s1;                                           \
            red[PAR][1][wid] = s2;                                           \
            red[PAR][2][wid] = s3;                                           \
        }                                                                    \
        __syncthreads();                                                     \
        float t1 = 0.f, t2 = 0.f, t3 = 0.f;                                  \
        _Pragma("unroll")                                                    \
        for (int w = 0; w < 8; w++) {                                        \
            t1 += red[PAR][0][w];                                            \
            t2 += red[PAR][1][w];                                            \
            t3 += red[PAR][2][w];                                            \
        }                                                                    \
        const float rs3     = rs * rs * rs;                                  \
        const float pd_var  = -0.5f * t1 * rs3;                              \
        const float pd_mean = -t2 * rs + pd_var * (-2.0f * inv_d) * t3;      \
        const float coef    = pd_var * (2.0f * inv_d);                       \
        const float cmean   = pd_mean * inv_d;                               \
        float ov[8];                                                         \
        _Pragma("unroll")                                                    \
        for (int k = 0; k < 8; k++) {                                        \
            const float pdxl = dyv[k] * gv[k];                               \
            ov[k] = fmaf(pdxl, rs, fmaf(coef, xh[k], cmean));                \
            ag[k] = fmaf(dyv[k] * xh[k], rs, ag[k]);                         \
            ab[k] += dyv[k];                                                 \
        }                                                                    \
        ov[0] += ds0.x; ov[1] += ds0.y; ov[2] += ds0.z; ov[3] += ds0.w;      \
        ov[4] += ds1.x; ov[5] += ds1.y; ov[6] += ds1.z; ov[7] += ds1.w;      \
        __stcs((float4*)(out + base + c0),                                   \
               make_float4(ov[0], ov[1], ov[2], ov[3]));                     \
        __stcs((float4*)(out + base + c1),                                   \
               make_float4(ov[4], ov[5], ov[6], ov[7]));                     \
    }

    // ---- prologue: rows bid (A) and bid+GRID (B) in flight ----
    LOADBUF(A, bid);
    LOADBUF(B, bid + GRID);

    int par = 0;
    for (int r = bid; r < ROWS; r += 2 * GRID) {
        STEP(A, r, r + 2 * GRID, par); par ^= 1;
        if (r + GRID < ROWS) {
            STEP(B, r + GRID, r + 3 * GRID, par); par ^= 1;
        }
    }

    // flush dgamma/dbeta partials: 296 CTAs * 4096 atomics -> negligible
    float* gout = out + (size_t)ROWS * HF;
    float* bout = gout + HF;
    #pragma unroll
    for (int k = 0; k < 4; k++) {
        atomicAdd(gout + c0 + k, ag[k]);
        atomicAdd(gout + c1 + k, ag[4 + k]);
        atomicAdd(bout + c0 + k, ab[k]);
        atomicAdd(bout + c1 + k, ab[4 + k]);
    }
}

extern "C" void kernel_launch(void* const* d_in, const int* in_sizes, int n_in,
                              void* d_out, int out_size) {
    const float* dy    = (const float*)d_in[0];
    const float* x1    = (const float*)d_in[1];
    const float* x2    = (const float*)d_in[2];
    const float* rstd  = (const float*)d_in[3];
    const float* mean  = (const float*)d_in[4];
    const float* gamma = (const float*)d_in[5];
    const float* dsum  = (const float*)d_in[6];
    float* out = (float*)d_out;

    // zero the dgamma/dbeta region via a memset node (cheap, capturable)
    cudaMemsetAsync(out + (size_t)ROWS * HF, 0, 2 * HF * sizeof(float));

    ln_bwd_kernel<<<GRID, THREADS>>>(dy, x1, x2, rstd, mean, gamma, dsum, out);
}

// round 14
// speedup vs baseline: 1.0368x; 1.0368x over previous
#include <cuda_runtime.h>

// LayerNorm backward fused: golden_x [B,S,H], golden_gamma [H], golden_beta [H]
// B=4, S=4096, H=2048, fp32. Output layout: [x | gamma | beta] concatenated.
// R12 (final): exact R9 — best verified configuration.
//   2 CTAs/SM x 256 thr, 8 cols/thread, distance-2 double-buffered register
//   prefetch of dy/x1/x2 (127 regs), dsum issued pre-barrier / consumed
//   post-barrier, single-barrier double-buffered cross-warp reduction,
//   streaming ld/st, register-accumulated dgamma/dbeta flushed via atomics,
//   param-grad region zeroed by a memset graph node.

#define HF 2048
#define ROWS 16384           // B*S
#define THREADS 256
#define GRID 296             // 148 SMs * 2 CTAs/SM

__global__ __launch_bounds__(THREADS, 2) void ln_bwd_kernel(
    const float* __restrict__ dy,
    const float* __restrict__ x1,
    const float* __restrict__ x2,
    const float* __restrict__ rstd,
    const float* __restrict__ mean,
    const float* __restrict__ gamma,
    const float* __restrict__ dsum,
    float* __restrict__ out)
{
    __shared__ float red[2][3][8];

    const int tid  = threadIdx.x;
    const int lane = tid & 31;
    const int wid  = tid >> 5;
    const int bid  = blockIdx.x;

    const int c0 = 4 * tid;          // 0..1020
    const int c1 = c0 + HF / 2;      // 1024..2044

    const float4 g0 = *(const float4*)(gamma + c0);
    const float4 g1 = *(const float4*)(gamma + c1);
    float gv[8] = {g0.x, g0.y, g0.z, g0.w, g1.x, g1.y, g1.z, g1.w};

    float ag[8] = {0.f, 0.f, 0.f, 0.f, 0.f, 0.f, 0.f, 0.f};
    float ab[8] = {0.f, 0.f, 0.f, 0.f, 0.f, 0.f, 0.f, 0.f};

    const float inv_d = 1.0f / (float)HF;

    // ---- two register buffer sets: dy, x1, x2 (+ mean/rstd scalars) ----
    float4 Ady0, Ady1, Aa0, Aa1, Ab0, Ab1; float Amu = 0.f, Ars = 0.f;
    float4 Bdy0, Bdy1, Ba0, Ba1, Bb0, Bb1; float Bmu = 0.f, Brs = 0.f;

    #define LOADBUF(P, row)                                                  \
        if ((row) < ROWS) {                                                  \
            const size_t _b = (size_t)(row) * HF;                            \
            P##dy0 = __ldcs((const float4*)(dy + _b + c0));                  \
            P##dy1 = __ldcs((const float4*)(dy + _b + c1));                  \
            P##a0  = __ldcs((const float4*)(x1 + _b + c0));                  \
            P##a1  = __ldcs((const float4*)(x1 + _b + c1));                  \
            P##b0  = __ldcs((const float4*)(x2 + _b + c0));                  \
            P##b1  = __ldcs((const float4*)(x2 + _b + c1));                  \
            P##mu  = __ldcs(mean + (row));                                   \
            P##rs  = __ldcs(rstd + (row));                                   \
        }

    // Consume buffer P (row `row`), refill P for row `nrow`, do full row work.
    #define STEP(P, row, nrow, PAR)                                          \
    {                                                                        \
        const size_t base = (size_t)(row) * HF;                              \
        /* consume buffer into locals (frees P for the refill below) */      \
        float dyv[8] = {P##dy0.x, P##dy0.y, P##dy0.z, P##dy0.w,              \
                        P##dy1.x, P##dy1.y, P##dy1.z, P##dy1.w};             \
        const float mu = P##mu;                                              \
        const float rs = P##rs;                                              \
        float xh[8]  = {P##a0.x + P##b0.x - mu, P##a0.y + P##b0.y - mu,      \
                        P##a0.z + P##b0.z - mu, P##a0.w + P##b0.w - mu,      \
                        P##a1.x + P##b1.x - mu, P##a1.y + P##b1.y - mu,      \
                        P##a1.z + P##b1.z - mu, P##a1.w + P##b1.w - mu};     \
        /* dsum for THIS row: issued now, consumed post-barrier */           \
        const float4 ds0 = __ldcs((const float4*)(dsum + base + c0));        \
        const float4 ds1 = __ldcs((const float4*)(dsum + base + c1));        \
        /* refill buffer: distance-2 prefetch */                             \
        LOADBUF(P, nrow);                                                    \
        /* local partial sums */                                             \
        float s1 = 0.f, s2 = 0.f, s3 = 0.f;                                  \
        _Pragma("unroll")                                                    \
        for (int k = 0; k < 8; k++) {                                        \
            const float pdxl = dyv[k] * gv[k];                               \
            s1 = fmaf(pdxl, xh[k], s1);                                      \
            s2 += pdxl;                                                      \
            s3 += xh[k];                                                     \
        }                                                                    \
        _Pragma("unroll")                                                    \
        for (int off = 16; off > 0; off >>= 1) {                             \
            s1 += __shfl_xor_sync(0xFFFFFFFFu, s1, off);                     \
            s2 += __shfl_xor_sync(0xFFFFFFFFu, s2, off);                     \
            s3 += __shfl_xor_sync(0xFFFFFFFFu, s3, off);                     \
        }                                                                    \
        if (lane == 0) {                                                     \
            red[PAR][0][wid] = s1;                                           \
            red[PAR][1][wid] = s2;                                           \
            red[PAR][2][wid] = s3;                                           \
        }                                                                    \
        __syncthreads();                                                     \
        float t1 = 0.f, t2 = 0.f, t3 = 0.f;                                  \
        _Pragma("unroll")                                                    \
        for (int w = 0; w < 8; w++) {                                        \
            t1 += red[PAR][0][w];                                            \
            t2 += red[PAR][1][w];                                            \
            t3 += red[PAR][2][w];                                            \
        }                                                                    \
        const float rs3     = rs * rs * rs;                                  \
        const float pd_var  = -0.5f * t1 * rs3;                              \
        const float pd_mean = -t2 * rs + pd_var * (-2.0f * inv_d) * t3;      \
        const float coef    = pd_var * (2.0f * inv_d);                       \
        const float cmean   = pd_mean * inv_d;                               \
        float ov[8];                                                         \
        _Pragma("unroll")                                                    \
        for (int k = 0; k < 8; k++) {                                        \
            const float pdxl = dyv[k] * gv[k];                               \
            ov[k] = fmaf(pdxl, rs, fmaf(coef, xh[k], cmean));                \
            ag[k] = fmaf(dyv[k] * xh[k], rs, ag[k]);                         \
            ab[k] += dyv[k];                                                 \
        }                                                                    \
        ov[0] += ds0.x; ov[1] += ds0.y; ov[2] += ds0.z; ov[3] += ds0.w;      \
        ov[4] += ds1.x; ov[5] += ds1.y; ov[6] += ds1.z; ov[7] += ds1.w;      \
        __stcs((float4*)(out + base + c0),                                   \
               make_float4(ov[0], ov[1], ov[2], ov[3]));                     \
        __stcs((float4*)(out + base + c1),                                   \
               make_float4(ov[4], ov[5], ov[6], ov[7]));                     \
    }

    // ---- prologue: rows bid (A) and bid+GRID (B) in flight ----
    LOADBUF(A, bid);
    LOADBUF(B, bid + GRID);

    int par = 0;
    for (int r = bid; r < ROWS; r += 2 * GRID) {
        STEP(A, r, r + 2 * GRID, par); par ^= 1;
        if (r + GRID < ROWS) {
            STEP(B, r + GRID, r + 3 * GRID, par); par ^= 1;
        }
    }

    // flush dgamma/dbeta partials: 296 CTAs * 4096 atomics -> negligible
    float* gout = out + (size_t)ROWS * HF;
    float* bout = gout + HF;
    #pragma unroll
    for (int k = 0; k < 4; k++) {
        atomicAdd(gout + c0 + k, ag[k]);
        atomicAdd(gout + c1 + k, ag[4 + k]);
        atomicAdd(bout + c0 + k, ab[k]);
        atomicAdd(bout + c1 + k, ab[4 + k]);
    }
}

extern "C" void kernel_launch(void* const* d_in, const int* in_sizes, int n_in,
                              void* d_out, int out_size) {
    const float* dy    = (const float*)d_in[0];
    const float* x1    = (const float*)d_in[1];
    const float* x2    = (const float*)d_in[2];
    const float* rstd  = (const float*)d_in[3];
    const float* mean  = (const float*)d_in[4];
    const float* gamma = (const float*)d_in[5];
    const float* dsum  = (const float*)d_in[6];
    float* out = (float*)d_out;

    // zero the dgamma/dbeta region (2*HF floats) via a memset node:
    // cheaper than a kernel launch, graph-capturable, no alloc/free.
    cudaMemsetAsync(out + (size_t)ROWS * HF, 0, 2 * HF * sizeof(float));

    ln_bwd_kernel<<<GRID, THREADS>>>(dy, x1, x2, rstd, mean, gamma, dsum, out);
}